// round 12
// baseline (speedup 1.0000x reference)
#include <cuda_runtime.h>
#include <cuda_bf16.h>
#include <mma.h>
#include <cstdint>
#include <cstddef>

using namespace nvcuda;

// Shapes: x[8,256,128,128] f32, kpts[8,4096,2], W[128,256], b[128] -> out[8,4096,128] f32
#define NB 8
#define NC 256
#define NPIX 16384
#define NE 128
#define NPTS 4096
#define NTILES 1024           // NB * NPIX/128
#define GRID1 148
#define NTHR 512

// SMEM geometry (float elements). Strides = 16 mod 128 bytes -> conflict-free frag rows.
#define WLDF 260              // W row stride: 256 + 4 pad floats (1040B)
#define PLDF 132              // X row stride: 128 + 4 pad floats (528B)
#define SM_W_OFF 0
#define SM_X_OFF (128 * WLDF * 4)                 // 133120
#define SM_TOT   (SM_X_OFF + 128 * PLDF * 4)      // 200704 B

// Scratch: Wx[b, pixel, e] fp32 (64 MiB)
__device__ float g_wx[(size_t)NB * NPIX * NE];

static __device__ __forceinline__ float to_tf32(float f) {
    float r;
    asm("cvt.rna.tf32.f32 %0, %1;" : "=f"(r) : "f"(f));
    return r;
}

// ===== Kernel 1: Wx[b,pix,e] = sum_c W[e,c] * x[b,c,pix]  (single-term TF32 WMMA) =====
// X channel-major in SMEM (contiguous float4 STS); consumed as col_major matrix_a.
__global__ void __launch_bounds__(NTHR, 1) k1_whiten(const float* __restrict__ x,
                                                     const float* __restrict__ wmat,
                                                     int t0, int t1) {
    extern __shared__ char smem[];
    float* Ws = (float*)(smem + SM_W_OFF);
    float* Xs = (float*)(smem + SM_X_OFF);

    const int tid = threadIdx.x;
    const int wid = tid >> 5;
    const int wm = wid & 3;          // pixel sub-tile (32 rows)
    const int wn = wid >> 2;         // E sub-tile (32 cols)

    // ---- W prologue: [128 E][256 c] floats, pre-rounded to tf32 ----
    for (int q = tid; q < 16384; q += NTHR) {
        int e = q >> 7, c2 = q & 127;
        float2 v = *(const float2*)(wmat + e * 256 + c2 * 2);
        Ws[e * WLDF + c2 * 2 + 0] = to_tf32(v.x);
        Ws[e * WLDF + c2 * 2 + 1] = to_tf32(v.y);
    }

    float4 v[8];
#define LOAD_CHUNK(Tv, ck)                                                           \
    do {                                                                             \
        const float* xb_ = x + (size_t)((Tv) >> 7) * NC * NPIX + (((Tv) & 127) << 7) \
                         + (size_t)(ck) * 128 * NPIX;                                \
        _Pragma("unroll")                                                            \
        for (int j = 0; j < 8; j++) {                                                \
            int q = j * NTHR + tid;                                                  \
            v[j] = ((const float4*)(xb_ + (size_t)(q >> 5) * NPIX))[q & 31];         \
        }                                                                            \
    } while (0)

    LOAD_CHUNK(t0 + blockIdx.x, 0);
    __syncthreads();   // W tile ready

    for (int T = t0 + blockIdx.x; T < t1; T += GRID1) {
        const int b = T >> 7;
        const int pix0 = (T & 127) << 7;

        wmma::fragment<wmma::accumulator, 16, 16, 8, float> acc[2][2];
#pragma unroll
        for (int mi = 0; mi < 2; mi++)
#pragma unroll
            for (int ni = 0; ni < 2; ni++)
                wmma::fill_fragment(acc[mi][ni], 0.0f);

        for (int chunk = 0; chunk < 2; chunk++) {
            // ---- STS staged chunk: channel-major, contiguous 16B stores, tf32-rounded ----
#pragma unroll
            for (int j = 0; j < 8; j++) {
                int q = j * NTHR + tid;
                int ch = q >> 5, p4 = q & 31;
                float4 t = v[j];
                t.x = to_tf32(t.x); t.y = to_tf32(t.y);
                t.z = to_tf32(t.z); t.w = to_tf32(t.w);
                *(float4*)(Xs + ch * PLDF + p4 * 4) = t;
            }
            __syncthreads();

            // ---- prefetch next chunk into regs (overlaps with MMA below) ----
            {
                int nT = (chunk == 0) ? T : T + GRID1;
                int nck = chunk ^ 1;
                if (nT < t1) LOAD_CHUNK(nT, nck);
            }

            // ---- MMA over this chunk: 16 k-steps of 8 ----
#pragma unroll
            for (int ks = 0; ks < 16; ks++) {
                const int kb = ks * 8;                 // local channel offset
                const int kg = chunk * 128 + kb;       // global (for W)
                wmma::fragment<wmma::matrix_a, 16, 16, 8, wmma::precision::tf32, wmma::col_major> a[2];
#pragma unroll
                for (int mi = 0; mi < 2; mi++)
                    wmma::load_matrix_sync(a[mi], Xs + kb * PLDF + wm * 32 + mi * 16, PLDF);
#pragma unroll
                for (int ni = 0; ni < 2; ni++) {
                    wmma::fragment<wmma::matrix_b, 16, 16, 8, wmma::precision::tf32, wmma::col_major> bb;
                    wmma::load_matrix_sync(bb, Ws + (wn * 32 + ni * 16) * WLDF + kg, WLDF);
#pragma unroll
                    for (int mi = 0; mi < 2; mi++)
                        wmma::mma_sync(acc[mi][ni], a[mi], bb, acc[mi][ni]);
                }
            }
            __syncthreads();   // MMAs done before X overwrite next chunk
        }

        // ---- epilogue: acc -> g_wx[b, pix, e] (E-contiguous) ----
        float* gp = g_wx + ((size_t)(b * NPIX + pix0)) * NE;
#pragma unroll
        for (int mi = 0; mi < 2; mi++)
#pragma unroll
            for (int ni = 0; ni < 2; ni++)
                wmma::store_matrix_sync(gp + (size_t)(wm * 32 + mi * 16) * NE + wn * 32 + ni * 16,
                                        acc[mi][ni], NE, wmma::mem_row_major);
    }
#undef LOAD_CHUNK
}

// ===== Kernel 2: bilinear gather on Wx + bias + L2-normalize =====
static __device__ __forceinline__ void corner_acc(const float* base, int xi, int yi,
                                                  bool valid, float wgt, int lane, float4& acc) {
    if (valid) {
        float4 vv = ((const float4*)(base + (size_t)(yi * 128 + xi) * NE))[lane];
        acc.x = fmaf(wgt, vv.x, acc.x);
        acc.y = fmaf(wgt, vv.y, acc.y);
        acc.z = fmaf(wgt, vv.z, acc.z);
        acc.w = fmaf(wgt, vv.w, acc.w);
    }
}

__global__ void __launch_bounds__(256) k2_sample(const float* __restrict__ kpts,
                                                 const float* __restrict__ bias,
                                                 float* __restrict__ out) {
    int gwarp = (blockIdx.x * 256 + threadIdx.x) >> 5;
    int lane = threadIdx.x & 31;
    if (gwarp >= NB * NPTS) return;
    int b = gwarp >> 12;

    float2 kp = ((const float2*)kpts)[gwarp];
    float ix = fmaf(kp.x, 64.0f, 63.5f);
    float iy = fmaf(kp.y, 64.0f, 63.5f);
    float x0f = floorf(ix), y0f = floorf(iy);
    float wx = ix - x0f, wy = iy - y0f;
    int x0 = (int)x0f, y0 = (int)y0f, x1 = x0 + 1, y1 = y0 + 1;
    float w00 = (1.f - wx) * (1.f - wy), w10 = wx * (1.f - wy);
    float w01 = (1.f - wx) * wy,         w11 = wx * wy;

    const float* base = g_wx + (size_t)b * NPIX * NE;
    float4 acc = ((const float4*)bias)[lane];

    bool vx0 = (x0 >= 0) & (x0 < 128), vx1 = (x1 >= 0) & (x1 < 128);
    bool vy0 = (y0 >= 0) & (y0 < 128), vy1 = (y1 >= 0) & (y1 < 128);
    corner_acc(base, x0, y0, vx0 && vy0, w00, lane, acc);
    corner_acc(base, x1, y0, vx1 && vy0, w10, lane, acc);
    corner_acc(base, x0, y1, vx0 && vy1, w01, lane, acc);
    corner_acc(base, x1, y1, vx1 && vy1, w11, lane, acc);

    float ss = acc.x * acc.x + acc.y * acc.y + acc.z * acc.z + acc.w * acc.w;
#pragma unroll
    for (int m = 16; m > 0; m >>= 1) ss += __shfl_xor_sync(0xFFFFFFFFu, ss, m);
    float inv = 1.0f / fmaxf(sqrtf(ss), 1e-12f);
    acc.x *= inv; acc.y *= inv; acc.z *= inv; acc.w *= inv;
    ((float4*)(out + (size_t)gwarp * NE))[lane] = acc;
}

extern "C" void kernel_launch(void* const* d_in, const int* in_sizes, int n_in,
                              void* d_out, int out_size) {
    const float* x    = (const float*)d_in[0];
    const float* kpts = (const float*)d_in[1];
    const float* wmat = (const float*)d_in[2];
    const float* bias = (const float*)d_in[3];
    float* out = (float*)d_out;

    cudaFuncSetAttribute(k1_whiten, cudaFuncAttributeMaxDynamicSharedMemorySize, SM_TOT);
    k1_whiten<<<GRID1, NTHR, SM_TOT>>>(x, wmat, 0, NTILES);
    k2_sample<<<(NB * NPTS) / 8, 256>>>(kpts, bias, out);
    // Probes: identical k1 work over tiles [0,148) — idempotent rewrite of the same
    // g_wx values (deterministic). They occupy launch positions 3-5 so ncu's fixed
    // skip window (absolute launch #8/#10/#14) lands on k1-representative work.
    k1_whiten<<<GRID1, NTHR, SM_TOT>>>(x, wmat, 0, GRID1);
    k1_whiten<<<GRID1, NTHR, SM_TOT>>>(x, wmat, 0, GRID1);
    k1_whiten<<<GRID1, NTHR, SM_TOT>>>(x, wmat, 0, GRID1);
}

// round 14
// speedup vs baseline: 1.5694x; 1.5694x over previous
#include <cuda_runtime.h>
#include <cuda_bf16.h>
#include <mma.h>
#include <cstdint>
#include <cstddef>

using namespace nvcuda;

// Shapes: x[8,256,128,128] f32, kpts[8,4096,2], W[128,256], b[128] -> out[8,4096,128] f32
#define NB 8
#define NC 256
#define NPIX 16384
#define NE 128
#define NPTS 4096
#define NTILES 1024           // NB * NPIX/128
#define GRID1 148
#define NTHR 256

// SMEM geometry (float elements), strides chosen so wmma frag-load lane
// footprints tile disjoint bank groups: WLDF%32==8, PLDF%32==16.
#define WLDF 264              // W row stride (1056B)
#define PLDF 144              // X row stride (576B), 16B-aligned rows
#define SM_W_OFF 0
#define SM_X_OFF (128 * WLDF * 4)                 // 135168
#define XBUF_B   (64 * PLDF * 4)                  // 36864 per buffer
#define SM_TOT   (SM_X_OFF + 2 * XBUF_B)          // 208896 B

// Scratch: Wx[b, pixel, e] fp32 (64 MiB)
__device__ float g_wx[(size_t)NB * NPIX * NE];

static __device__ __forceinline__ float to_tf32(float f) {
    float r;
    asm("cvt.rna.tf32.f32 %0, %1;" : "=f"(r) : "f"(f));
    return r;
}
static __device__ __forceinline__ uint32_t smem_u32(const void* p) {
    uint32_t a;
    asm("{ .reg .u64 t; cvta.to.shared.u64 t, %1; cvt.u32.u64 %0, t; }" : "=r"(a) : "l"(p));
    return a;
}
static __device__ __forceinline__ void cp_async16(uint32_t saddr, const float* g) {
    asm volatile("cp.async.cg.shared.global [%0], [%1], 16;" :: "r"(saddr), "l"(g));
}
#define CP_COMMIT() asm volatile("cp.async.commit_group;" ::: "memory")
#define CP_WAIT0()  asm volatile("cp.async.wait_group 0;" ::: "memory")

// Issue one 64-channel x 128-pixel chunk copy (32KB) via cp.async, register-free.
static __device__ __forceinline__ void copy_chunk(const float* __restrict__ x,
                                                  int T, int ck, uint32_t xbuf, int tid) {
    const float* src = x + (size_t)(T >> 7) * NC * NPIX + ((T & 127) << 7)
                     + (size_t)ck * 64 * NPIX;
#pragma unroll
    for (int j = 0; j < 8; j++) {
        int q = j * NTHR + tid;
        int ch = q >> 5, p4 = q & 31;                       // ch<64, p4<32
        cp_async16(xbuf + (uint32_t)(ch * PLDF + p4 * 4) * 4,
                   src + (size_t)ch * NPIX + p4 * 4);
    }
    CP_COMMIT();
}

// ===== Kernel 1: Wx[b,pix,e] = sum_c W[e,c] * x[b,c,pix]  (TF32 WMMA, cp.async pipeline) =====
__global__ void __launch_bounds__(NTHR, 1) k1_whiten(const float* __restrict__ x,
                                                     const float* __restrict__ wmat) {
    extern __shared__ char smem[];
    float* Ws = (float*)(smem + SM_W_OFF);
    float* Xb[2] = { (float*)(smem + SM_X_OFF), (float*)(smem + SM_X_OFF + XBUF_B) };
    uint32_t xbu[2] = { smem_u32(Xb[0]), smem_u32(Xb[1]) };

    const int tid = threadIdx.x;
    const int wid = tid >> 5;
    const int wm = wid & 3;          // pixel sub-tile (32 rows)
    const int wn = wid >> 2;         // E sub-tile (64 cols)

    // Kick off first chunk copy immediately (overlaps W prologue).
    int T0 = blockIdx.x;
    copy_chunk(x, T0, 0, xbu[0], tid);

    // ---- W prologue: [128 E][256 c] floats, pre-rounded to tf32, stride WLDF ----
    for (int q = tid; q < 16384; q += NTHR) {
        int e = q >> 7, c2 = q & 127;
        float2 v = *(const float2*)(wmat + e * 256 + c2 * 2);
        Ws[e * WLDF + c2 * 2 + 0] = to_tf32(v.x);
        Ws[e * WLDF + c2 * 2 + 1] = to_tf32(v.y);
    }

    for (int T = T0; T < NTILES; T += GRID1) {
        const int b = T >> 7;
        const int pix0 = (T & 127) << 7;

        wmma::fragment<wmma::accumulator, 16, 16, 8, float> acc[2][4];
#pragma unroll
        for (int mi = 0; mi < 2; mi++)
#pragma unroll
            for (int ni = 0; ni < 4; ni++)
                wmma::fill_fragment(acc[mi][ni], 0.0f);

#pragma unroll
        for (int c = 0; c < 4; c++) {
            CP_WAIT0();          // chunk c data resident in Xb[c&1]
            __syncthreads();     // all warps past MMA(c-2 on this buffer); data visible

            // issue copy for next chunk into the other buffer (overlaps MMA below)
            {
                int nT = (c == 3) ? T + GRID1 : T;
                int nc = (c == 3) ? 0 : c + 1;
                if (nT < NTILES) copy_chunk(x, nT, nc, xbu[(c + 1) & 1], tid);
            }

            const float* Xc = Xb[c & 1];
            // ---- MMA over this 64-channel chunk: 8 k-steps of 8 ----
#pragma unroll
            for (int ks = 0; ks < 8; ks++) {
                const int kb = ks * 8;               // channel offset within chunk
                const int kg = c * 64 + kb;          // global channel (for W)
                wmma::fragment<wmma::matrix_a, 16, 16, 8, wmma::precision::tf32, wmma::col_major> a[2];
#pragma unroll
                for (int mi = 0; mi < 2; mi++) {
                    wmma::load_matrix_sync(a[mi], Xc + kb * PLDF + wm * 32 + mi * 16, PLDF);
#pragma unroll
                    for (int e = 0; e < a[mi].num_elements; e++)
                        a[mi].x[e] = to_tf32(a[mi].x[e]);
                }
#pragma unroll
                for (int ni = 0; ni < 4; ni++) {
                    wmma::fragment<wmma::matrix_b, 16, 16, 8, wmma::precision::tf32, wmma::col_major> bb;
                    wmma::load_matrix_sync(bb, Ws + (wn * 64 + ni * 16) * WLDF + kg, WLDF);
#pragma unroll
                    for (int mi = 0; mi < 2; mi++)
                        wmma::mma_sync(acc[mi][ni], a[mi], bb, acc[mi][ni]);
                }
            }
        }

        // ---- epilogue: acc -> g_wx[b, pix, e] (E-contiguous); overlaps next copy ----
        float* gp = g_wx + ((size_t)(b * NPIX + pix0)) * NE;
#pragma unroll
        for (int mi = 0; mi < 2; mi++)
#pragma unroll
            for (int ni = 0; ni < 4; ni++)
                wmma::store_matrix_sync(gp + (size_t)(wm * 32 + mi * 16) * NE + wn * 64 + ni * 16,
                                        acc[mi][ni], NE, wmma::mem_row_major);
    }
}

// ===== Kernel 2: bilinear gather on Wx + bias + L2-normalize =====
static __device__ __forceinline__ void corner_acc(const float* base, int xi, int yi,
                                                  bool valid, float wgt, int lane, float4& acc) {
    if (valid) {
        float4 vv = ((const float4*)(base + (size_t)(yi * 128 + xi) * NE))[lane];
        acc.x = fmaf(wgt, vv.x, acc.x);
        acc.y = fmaf(wgt, vv.y, acc.y);
        acc.z = fmaf(wgt, vv.z, acc.z);
        acc.w = fmaf(wgt, vv.w, acc.w);
    }
}

__global__ void __launch_bounds__(256) k2_sample(const float* __restrict__ kpts,
                                                 const float* __restrict__ bias,
                                                 float* __restrict__ out) {
    int gwarp = (blockIdx.x * 256 + threadIdx.x) >> 5;
    int lane = threadIdx.x & 31;
    if (gwarp >= NB * NPTS) return;
    int b = gwarp >> 12;

    float2 kp = ((const float2*)kpts)[gwarp];
    float ix = fmaf(kp.x, 64.0f, 63.5f);
    float iy = fmaf(kp.y, 64.0f, 63.5f);
    float x0f = floorf(ix), y0f = floorf(iy);
    float wx = ix - x0f, wy = iy - y0f;
    int x0 = (int)x0f, y0 = (int)y0f, x1 = x0 + 1, y1 = y0 + 1;
    float w00 = (1.f - wx) * (1.f - wy), w10 = wx * (1.f - wy);
    float w01 = (1.f - wx) * wy,         w11 = wx * wy;

    const float* base = g_wx + (size_t)b * NPIX * NE;
    float4 acc = ((const float4*)bias)[lane];

    bool vx0 = (x0 >= 0) & (x0 < 128), vx1 = (x1 >= 0) & (x1 < 128);
    bool vy0 = (y0 >= 0) & (y0 < 128), vy1 = (y1 >= 0) & (y1 < 128);
    corner_acc(base, x0, y0, vx0 && vy0, w00, lane, acc);
    corner_acc(base, x1, y0, vx1 && vy0, w10, lane, acc);
    corner_acc(base, x0, y1, vx0 && vy1, w01, lane, acc);
    corner_acc(base, x1, y1, vx1 && vy1, w11, lane, acc);

    float ss = acc.x * acc.x + acc.y * acc.y + acc.z * acc.z + acc.w * acc.w;
#pragma unroll
    for (int m = 16; m > 0; m >>= 1) ss += __shfl_xor_sync(0xFFFFFFFFu, ss, m);
    float inv = 1.0f / fmaxf(sqrtf(ss), 1e-12f);
    acc.x *= inv; acc.y *= inv; acc.z *= inv; acc.w *= inv;
    ((float4*)(out + (size_t)gwarp * NE))[lane] = acc;
}

extern "C" void kernel_launch(void* const* d_in, const int* in_sizes, int n_in,
                              void* d_out, int out_size) {
    const float* x    = (const float*)d_in[0];
    const float* kpts = (const float*)d_in[1];
    const float* wmat = (const float*)d_in[2];
    const float* bias = (const float*)d_in[3];
    float* out = (float*)d_out;

    cudaFuncSetAttribute(k1_whiten, cudaFuncAttributeMaxDynamicSharedMemorySize, SM_TOT);
    k1_whiten<<<GRID1, NTHR, SM_TOT>>>(x, wmat);
    k2_sample<<<(NB * NPTS) / 8, 256>>>(kpts, bias, out);
}

// round 16
// speedup vs baseline: 2.9530x; 1.8816x over previous
#include <cuda_runtime.h>
#include <cuda_fp16.h>
#include <mma.h>
#include <cstdint>
#include <cstddef>

using namespace nvcuda;

// Shapes: x[8,256,128,128] f32, kpts[8,4096,2], W[128,256], b[128] -> out[8,4096,128] f32
#define NB 8
#define NC 256
#define NPIX 16384
#define NE 128
#define NPTS 4096
#define NTILES 1024           // NB * NPIX/128
#define GRID1 296             // 2 CTAs per SM
#define NTHR 256

// SMEM geometry (half elements). Row strides = 16 mod 128 bytes.
#define WLDH 264              // W row stride (528B)
#define PLDH 136              // X row stride (272B)
#define SM_W_OFF 0
#define SM_X_OFF (128 * WLDH * 2)                 // 67584
#define XBUF_B   (64 * PLDH * 2)                  // 17408 per buffer
#define SM_TOT   (SM_X_OFF + 2 * XBUF_B)          // 102400 B -> 2 CTAs/SM

// Scratch: Wx[b, pixel, e] fp32 (64 MiB)
__device__ float g_wx[(size_t)NB * NPIX * NE];

// ===== Kernel 1: Wx[b,pix,e] = sum_c W[e,c] * x[b,c,pix]  (single-term fp16 WMMA) =====
// fp16 mantissa (10 bits) == tf32 mantissa -> same error as R12's measured 2.96e-4.
// 100KB SMEM -> 2 CTAs/SM -> 2x warps for latency hiding (k1 is latency-bound per R12 probe).
__global__ void __launch_bounds__(NTHR, 2) k1_whiten(const float* __restrict__ x,
                                                     const float* __restrict__ wmat) {
    extern __shared__ char smem[];
    __half* Ws = (__half*)(smem + SM_W_OFF);
    __half* Xb[2] = { (__half*)(smem + SM_X_OFF), (__half*)(smem + SM_X_OFF + XBUF_B) };

    const int tid = threadIdx.x;
    const int wid = tid >> 5;
    const int wm = wid & 3;          // pixel sub-tile (32 rows)
    const int wn = wid >> 2;         // E sub-tile (64 cols)

    // staging registers: 8 float4/thread = one 64ch x 128pix chunk per CTA
    float4 v[8];
#define LOAD_CHUNK(Tv, ck)                                                           \
    do {                                                                             \
        const float* xb_ = x + (size_t)((Tv) >> 7) * NC * NPIX + (((Tv) & 127) << 7) \
                         + (size_t)(ck) * 64 * NPIX;                                 \
        _Pragma("unroll")                                                            \
        for (int j = 0; j < 8; j++) {                                                \
            int q = j * NTHR + tid;                                                  \
            v[j] = ((const float4*)(xb_ + (size_t)(q >> 5) * NPIX))[q & 31];         \
        }                                                                            \
    } while (0)

    LOAD_CHUNK(blockIdx.x, 0);   // overlap first chunk load with W prologue

    // ---- W prologue: [128 E][256 c] -> fp16, row stride WLDH ----
    for (int q = tid; q < 16384; q += NTHR) {
        int e = q >> 7, c2 = q & 127;
        float2 w = *(const float2*)(wmat + e * 256 + c2 * 2);
        *(__half2*)(Ws + e * WLDH + c2 * 2) = __floats2half2_rn(w.x, w.y);
    }

    for (int T = blockIdx.x; T < NTILES; T += GRID1) {
        const int b = T >> 7;
        const int pix0 = (T & 127) << 7;

        wmma::fragment<wmma::accumulator, 16, 16, 16, float> acc[2][4];
#pragma unroll
        for (int mi = 0; mi < 2; mi++)
#pragma unroll
            for (int ni = 0; ni < 4; ni++)
                wmma::fill_fragment(acc[mi][ni], 0.0f);

#pragma unroll
        for (int c = 0; c < 4; c++) {            // 4 chunks of 64 channels
            __half* Xc = Xb[c & 1];
            // ---- STS staged chunk: channel-major fp16, contiguous 8B stores ----
            // buf[c&1] was last read by MMA(c-2); sync(c-1) already ordered that.
#pragma unroll
            for (int j = 0; j < 8; j++) {
                int q = j * NTHR + tid;
                int ch = q >> 5, p4 = q & 31;
                float4 t = v[j];
                __half2 h0 = __floats2half2_rn(t.x, t.y);
                __half2 h1 = __floats2half2_rn(t.z, t.w);
                *(uint2*)(Xc + ch * PLDH + p4 * 4) =
                    make_uint2(*(uint32_t*)&h0, *(uint32_t*)&h1);
            }
            __syncthreads();

            // ---- prefetch next chunk into regs (overlaps with MMA below) ----
            {
                int nT = (c == 3) ? T + GRID1 : T;
                int nc = (c == 3) ? 0 : c + 1;
                if (nT < NTILES) LOAD_CHUNK(nT, nc);
            }

            // ---- MMA over this chunk: 4 k-steps of 16 ----
#pragma unroll
            for (int ks = 0; ks < 4; ks++) {
                const int kb = ks * 16;              // channel offset within chunk
                const int kg = c * 64 + kb;          // global channel (for W)
                wmma::fragment<wmma::matrix_a, 16, 16, 16, __half, wmma::col_major> a[2];
#pragma unroll
                for (int mi = 0; mi < 2; mi++)
                    wmma::load_matrix_sync(a[mi], Xc + kb * PLDH + wm * 32 + mi * 16, PLDH);
#pragma unroll
                for (int ni = 0; ni < 4; ni++) {
                    wmma::fragment<wmma::matrix_b, 16, 16, 16, __half, wmma::col_major> bb;
                    wmma::load_matrix_sync(bb, Ws + (wn * 64 + ni * 16) * WLDH + kg, WLDH);
#pragma unroll
                    for (int mi = 0; mi < 2; mi++)
                        wmma::mma_sync(acc[mi][ni], a[mi], bb, acc[mi][ni]);
                }
            }
        }

        // ---- epilogue: acc -> g_wx[b, pix, e] (E-contiguous) ----
        float* gp = g_wx + ((size_t)(b * NPIX + pix0)) * NE;
#pragma unroll
        for (int mi = 0; mi < 2; mi++)
#pragma unroll
            for (int ni = 0; ni < 4; ni++)
                wmma::store_matrix_sync(gp + (size_t)(wm * 32 + mi * 16) * NE + wn * 64 + ni * 16,
                                        acc[mi][ni], NE, wmma::mem_row_major);
    }
#undef LOAD_CHUNK
}

// ===== Kernel 2: bilinear gather on Wx + bias + L2-normalize =====
static __device__ __forceinline__ void corner_acc(const float* base, int xi, int yi,
                                                  bool valid, float wgt, int lane, float4& acc) {
    if (valid) {
        float4 vv = ((const float4*)(base + (size_t)(yi * 128 + xi) * NE))[lane];
        acc.x = fmaf(wgt, vv.x, acc.x);
        acc.y = fmaf(wgt, vv.y, acc.y);
        acc.z = fmaf(wgt, vv.z, acc.z);
        acc.w = fmaf(wgt, vv.w, acc.w);
    }
}

__global__ void __launch_bounds__(256) k2_sample(const float* __restrict__ kpts,
                                                 const float* __restrict__ bias,
                                                 float* __restrict__ out) {
    int gwarp = (blockIdx.x * 256 + threadIdx.x) >> 5;
    int lane = threadIdx.x & 31;
    if (gwarp >= NB * NPTS) return;
    int b = gwarp >> 12;

    float2 kp = ((const float2*)kpts)[gwarp];
    float ix = fmaf(kp.x, 64.0f, 63.5f);
    float iy = fmaf(kp.y, 64.0f, 63.5f);
    float x0f = floorf(ix), y0f = floorf(iy);
    float wx = ix - x0f, wy = iy - y0f;
    int x0 = (int)x0f, y0 = (int)y0f, x1 = x0 + 1, y1 = y0 + 1;
    float w00 = (1.f - wx) * (1.f - wy), w10 = wx * (1.f - wy);
    float w01 = (1.f - wx) * wy,         w11 = wx * wy;

    const float* base = g_wx + (size_t)b * NPIX * NE;
    float4 acc = ((const float4*)bias)[lane];

    bool vx0 = (x0 >= 0) & (x0 < 128), vx1 = (x1 >= 0) & (x1 < 128);
    bool vy0 = (y0 >= 0) & (y0 < 128), vy1 = (y1 >= 0) & (y1 < 128);
    corner_acc(base, x0, y0, vx0 && vy0, w00, lane, acc);
    corner_acc(base, x1, y0, vx1 && vy0, w10, lane, acc);
    corner_acc(base, x0, y1, vx0 && vy1, w01, lane, acc);
    corner_acc(base, x1, y1, vx1 && vy1, w11, lane, acc);

    float ss = acc.x * acc.x + acc.y * acc.y + acc.z * acc.z + acc.w * acc.w;
#pragma unroll
    for (int m = 16; m > 0; m >>= 1) ss += __shfl_xor_sync(0xFFFFFFFFu, ss, m);
    float inv = 1.0f / fmaxf(sqrtf(ss), 1e-12f);
    acc.x *= inv; acc.y *= inv; acc.z *= inv; acc.w *= inv;
    ((float4*)(out + (size_t)gwarp * NE))[lane] = acc;
}

extern "C" void kernel_launch(void* const* d_in, const int* in_sizes, int n_in,
                              void* d_out, int out_size) {
    const float* x    = (const float*)d_in[0];
    const float* kpts = (const float*)d_in[1];
    const float* wmat = (const float*)d_in[2];
    const float* bias = (const float*)d_in[3];
    float* out = (float*)d_out;

    cudaFuncSetAttribute(k1_whiten, cudaFuncAttributeMaxDynamicSharedMemorySize, SM_TOT);
    k1_whiten<<<GRID1, NTHR, SM_TOT>>>(x, wmat);
    k2_sample<<<(NB * NPTS) / 8, 256>>>(kpts, bias, out);
}